// round 16
// baseline (speedup 1.0000x reference)
#include <cuda_runtime.h>
#include <cstdint>

#define OBS_LEN 8
#define PRED_LEN 12
#define BATCHN 65536
#define BLK 256
#define EPB 256          // elems per CTA -> grid = 256
#define HSTR 68          // row stride (floats) for h and c tiles: 64 + pad
#define WF_N 16384       // frag words/phase

// W in mma-B-fragment order (tf32 bits); packed input-term table [u<64][ty][mx,my,cb]
__device__ uint32_t g_wF[2][WF_N];
__device__ float    g_cmP[2][64 * 12];

// ---- smem float-offsets ----
#define SF_WF 0              // 16384
#define SF_H  16384          // 256*68 = 17408
#define SF_C  33792          // 17408
#define SF_CM 51200          // 768 (64*12)
#define SF_P0 51968          // 64
#define SF_P1 52032          // 64
#define SF_TOT 52096         // *4 = 208384 B

static __device__ __forceinline__ float tha(float x){
    float r; asm("tanh.approx.f32 %0, %1;" : "=f"(r) : "f"(x)); return r;
}
static __device__ __forceinline__ float sga(float x){
    return fmaf(0.5f, tha(0.5f * x), 0.5f);
}
static __device__ __forceinline__ uint32_t t32(float x){
    uint32_t r; asm("cvt.rna.tf32.f32 %0, %1;" : "=r"(r) : "f"(x)); return r;
}
static __device__ __forceinline__ void mma8(float* d, const uint32_t* a, const uint32_t* b){
    asm("mma.sync.aligned.m16n8k8.row.col.f32.tf32.tf32.f32 "
        "{%0,%1,%2,%3}, {%4,%5,%6,%7}, {%8,%9}, {%0,%1,%2,%3};"
        : "+f"(d[0]), "+f"(d[1]), "+f"(d[2]), "+f"(d[3])
        : "r"(a[0]), "r"(a[1]), "r"(a[2]), "r"(a[3]), "r"(b[0]), "r"(b[1]));
}

// ---------------------------------------------------------------------------
// Prep: input-term table (per unit u<64: [ty][mx,my,cb]) + B fragments (K=64).
// B layout (LDS.128-friendly): word = ((cc*2+tt)*32 + lane)*16 + ks*2 + idx,
// value = W[jj][k], jj = (2tt+(gid&1))*64 + 4cc+(gid>>1), k = ks*8+tig+idx*4.
// ---------------------------------------------------------------------------
__global__ void vlstm_prep(const float* __restrict__ ew, const float* __restrict__ eb,
                           const float* __restrict__ wih_e, const float* __restrict__ whh_e,
                           const float* __restrict__ bih_e, const float* __restrict__ bhh_e,
                           const float* __restrict__ dw, const float* __restrict__ db,
                           const float* __restrict__ wih_d, const float* __restrict__ whh_d,
                           const float* __restrict__ bih_d, const float* __restrict__ bhh_d)
{
    __shared__ float sMx[256], sMy[256], sCB[256];
    const int j = threadIdx.x;   // 0..255 = gate row
    for (int ph = 0; ph < 2; ph++) {
        const float* emb_w = ph ? dw : ew;
        const float* emb_b = ph ? db : eb;
        const float* wih   = ph ? wih_d : wih_e;
        const float* whh   = ph ? whh_d : whh_e;
        const float* bih   = ph ? bih_d : bih_e;
        const float* bhh   = ph ? bhh_d : bhh_e;
        float mx = 0.f, my = 0.f, mb = 0.f;
        #pragma unroll 8
        for (int e = 0; e < 64; e++) {
            float wv = wih[j * 64 + e];
            mx += wv * emb_w[e * 2 + 0];
            my += wv * emb_w[e * 2 + 1];
            mb += wv * emb_b[e];
        }
        sMx[j] = mx; sMy[j] = my; sCB[j] = mb + bih[j] + bhh[j];
        __syncthreads();

        if (j < 64) {
            const int u = j;
            #pragma unroll
            for (int ty = 0; ty < 4; ty++) {
                g_cmP[ph][u * 12 + ty * 3 + 0] = sMx[ty * 64 + u];
                g_cmP[ph][u * 12 + ty * 3 + 1] = sMy[ty * 64 + u];
                g_cmP[ph][u * 12 + ty * 3 + 2] = sCB[ty * 64 + u];
            }
        }
        for (int w = j; w < WF_N; w += 256) {
            int idx  = w & 1;
            int ks   = (w >> 1) & 7;
            int lane = (w >> 4) & 31;
            int tcc  = w >> 9;
            int tt = tcc & 1, cc = tcc >> 1;
            int tig = lane & 3, gid = lane >> 2;
            int unit = 4 * cc + (gid >> 1);
            int ty   = 2 * tt + (gid & 1);
            int jj   = ty * 64 + unit;
            int k    = ks * 8 + tig + idx * 4;
            g_wF[ph][w] = t32(whh[jj * 64 + k]);
        }
        __syncthreads();
    }
}

// ---------------------------------------------------------------------------
// One LSTM step. Warp-private rows; h updated in-place (__syncwarp fences).
// Fully-unrolled 16-chunk loop: ptxas overlaps chunk cc+1 B-loads/MMAs with
// chunk cc's MUFU epilogue. c in smem (conflict-free).
// ---------------------------------------------------------------------------
template <bool DEC>
static __device__ __forceinline__ void lstm_step(
    float* __restrict__ sm, int wbase, int gid, int tig,
    float px[2][2], float py[2][2],
    float pb0, float pb1,
    float* __restrict__ outp, int gbase)
{
    uint32_t* smu = (uint32_t*)sm;
    const int lane = gid * 4 + tig;

    // ---- A fragments (old h): 2 row-blocks x 8 k-steps x 4 regs ----
    uint32_t A[2][8][4];
    #pragma unroll
    for (int rb = 0; rb < 2; rb++) {
        const uint32_t* rp = smu + SF_H + (wbase + rb * 16 + gid) * HSTR + tig;
        #pragma unroll
        for (int ks = 0; ks < 8; ks++) {
            A[rb][ks][0] = rp[ks * 8];
            A[rb][ks][1] = rp[ks * 8 + 8 * HSTR];
            A[rb][ks][2] = rp[ks * 8 + 4];
            A[rb][ks][3] = rp[ks * 8 + 8 * HSTR + 4];
        }
    }
    __syncwarp();   // all lanes' A reads done before any lane overwrites h

    float rx[2][2], ry[2][2];
    if (DEC) {
        #pragma unroll
        for (int rb = 0; rb < 2; rb++)
            #pragma unroll
            for (int hi = 0; hi < 2; hi++) { rx[rb][hi] = 0.f; ry[rb][hi] = 0.f; }
    }

    #pragma unroll
    for (int cc = 0; cc < 16; cc++) {
        const int u = 4 * cc + tig;

        // input-term table (3 x LDS.128, broadcast across gid)
        float4 cmi = *(const float4*)(sm + SF_CM + u * 12);
        float4 cmf = *(const float4*)(sm + SF_CM + u * 12 + 4);
        float4 cmg = *(const float4*)(sm + SF_CM + u * 12 + 8);

        // c prefetch (conflict-free LDS.32)
        float cold[2][2];
        #pragma unroll
        for (int rb = 0; rb < 2; rb++)
            #pragma unroll
            for (int hi = 0; hi < 2; hi++)
                cold[rb][hi] = sm[SF_C + (wbase + rb * 16 + gid + hi * 8) * HSTR + u];

        float p0 = 0.f, p1 = 0.f;
        if (DEC) { p0 = sm[SF_P0 + u]; p1 = sm[SF_P1 + u]; }

        // B fragments: 4 x LDS.128 per tile (contiguous per-thread layout)
        uint32_t Bf[2][8][2];
        #pragma unroll
        for (int tt = 0; tt < 2; tt++) {
            const uint32_t* bp = smu + SF_WF + ((cc * 2 + tt) * 32 + lane) * 16;
            #pragma unroll
            for (int j2 = 0; j2 < 4; j2++) {
                uint4 v = *(const uint4*)(bp + j2 * 4);
                Bf[tt][2 * j2 + 0][0] = v.x; Bf[tt][2 * j2 + 0][1] = v.y;
                Bf[tt][2 * j2 + 1][0] = v.z; Bf[tt][2 * j2 + 1][1] = v.w;
            }
        }

        float acc[2][2][4];
        #pragma unroll
        for (int rb = 0; rb < 2; rb++)
            #pragma unroll
            for (int tt = 0; tt < 2; tt++)
                #pragma unroll
                for (int x = 0; x < 4; x++) acc[rb][tt][x] = 0.f;

        #pragma unroll
        for (int rb = 0; rb < 2; rb++)
            #pragma unroll
            for (int tt = 0; tt < 2; tt++)
                #pragma unroll
                for (int ks = 0; ks < 8; ks++)
                    mma8(acc[rb][tt], A[rb][ks], Bf[tt][ks]);

        // epilogue: tile0 cols (2tig,2tig+1)=(i,f), tile1=(g,o) of unit u
        #pragma unroll
        for (int rb = 0; rb < 2; rb++)
            #pragma unroll
            for (int hi = 0; hi < 2; hi++) {
                const int off = wbase + rb * 16 + gid + hi * 8;
                float pxl = px[rb][hi], pyl = py[rb][hi];
                float iv = acc[rb][0][2*hi+0] + fmaf(cmi.x, pxl, fmaf(cmi.y, pyl, cmi.z));
                float fv = acc[rb][0][2*hi+1] + fmaf(cmi.w, pxl, fmaf(cmf.x, pyl, cmf.y));
                float gv = acc[rb][1][2*hi+0] + fmaf(cmf.z, pxl, fmaf(cmf.w, pyl, cmg.x));
                float ov = acc[rb][1][2*hi+1] + fmaf(cmg.y, pxl, fmaf(cmg.z, pyl, cmg.w));
                float cn = fmaf(sga(fv), cold[rb][hi], sga(iv) * tha(gv));
                sm[SF_C + off * HSTR + u] = cn;
                float hn = sga(ov) * tha(cn);
                smu[SF_H + off * HSTR + u] = t32(hn);
                if (DEC) {
                    rx[rb][hi] = fmaf(hn, p0, rx[rb][hi]);
                    ry[rb][hi] = fmaf(hn, p1, ry[rb][hi]);
                }
            }
    }

    if (DEC) {
        #pragma unroll
        for (int rb = 0; rb < 2; rb++)
            #pragma unroll
            for (int hi = 0; hi < 2; hi++) {
                float vx = rx[rb][hi], vy = ry[rb][hi];
                vx += __shfl_xor_sync(0xffffffffu, vx, 1);
                vx += __shfl_xor_sync(0xffffffffu, vx, 2);
                vy += __shfl_xor_sync(0xffffffffu, vy, 1);
                vy += __shfl_xor_sync(0xffffffffu, vy, 2);
                vx += pb0; vy += pb1;
                px[rb][hi] = vx; py[rb][hi] = vy;   // next step's input (in-reg)
                if (tig == 0) {
                    const int off = rb * 16 + gid + hi * 8;
                    *(float2*)(outp + (size_t)(gbase + off) * 2) = make_float2(vx, vy);
                }
            }
    }
    __syncwarp();   // h/c stores visible before next step's A loads
}

// ---------------------------------------------------------------------------
// Main kernel
// ---------------------------------------------------------------------------
__global__ void __launch_bounds__(BLK, 1)
vlstm_main(const float* __restrict__ obs_rel,
           const float* __restrict__ h2p_w, const float* __restrict__ h2p_b,
           float* __restrict__ out)
{
    extern __shared__ float sm[];
    uint32_t* WF = (uint32_t*)(sm + SF_WF);

    const int tid  = threadIdx.x;
    const int wid  = tid >> 5;
    const int lane = tid & 31;
    const int gid  = lane >> 2;
    const int tig  = lane & 3;
    const int wbase = wid * 32;
    const int gbase = blockIdx.x * EPB + wbase;

    // ---- init: encoder weights/table, h2p, zero h and c ----
    for (int i = tid; i < WF_N; i += BLK) WF[i] = g_wF[0][i];
    if (tid < 192) {
        sm[SF_CM + tid] = g_cmP[0][tid];
        sm[SF_CM + 192 + tid] = g_cmP[0][192 + tid];
        sm[SF_CM + 384 + tid] = g_cmP[0][384 + tid];
        sm[SF_CM + 576 + tid] = g_cmP[0][576 + tid];
    }
    if (tid < 64) { sm[SF_P0 + tid] = h2p_w[tid]; sm[SF_P1 + tid] = h2p_w[64 + tid]; }
    for (int i = tid; i < EPB * HSTR; i += BLK) { sm[SF_H + i] = 0.f; sm[SF_C + i] = 0.f; }
    __syncthreads();

    float px[2][2], py[2][2];

    // ---- encoder: 8 steps ----
    #pragma unroll 1
    for (int t = 0; t < OBS_LEN; t++) {
        #pragma unroll
        for (int rb = 0; rb < 2; rb++)
            #pragma unroll
            for (int hi = 0; hi < 2; hi++) {
                int off = rb * 16 + gid + hi * 8;
                float2 p = *(const float2*)(obs_rel + (size_t)(t * BATCHN + gbase + off) * 2);
                px[rb][hi] = p.x; py[rb][hi] = p.y;
            }
        lstm_step<false>(sm, wbase, gid, tig, px, py, 0.f, 0.f, nullptr, gbase);
    }

    // ---- phase swap: decoder weights/table, reset c ----
    __syncthreads();
    for (int i = tid; i < WF_N; i += BLK) WF[i] = g_wF[1][i];
    if (tid < 192) {
        sm[SF_CM + tid] = g_cmP[1][tid];
        sm[SF_CM + 192 + tid] = g_cmP[1][192 + tid];
        sm[SF_CM + 384 + tid] = g_cmP[1][384 + tid];
        sm[SF_CM + 576 + tid] = g_cmP[1][576 + tid];
    }
    for (int i = tid; i < EPB * HSTR; i += BLK) sm[SF_C + i] = 0.f;
    __syncthreads();

    const float pb0 = h2p_b[0], pb1 = h2p_b[1];
    #pragma unroll
    for (int rb = 0; rb < 2; rb++)
        #pragma unroll
        for (int hi = 0; hi < 2; hi++) {
            int off = rb * 16 + gid + hi * 8;
            float2 p = *(const float2*)(obs_rel + (size_t)(7 * BATCHN + gbase + off) * 2);
            px[rb][hi] = p.x; py[rb][hi] = p.y;
        }

    // ---- decoder: 12 steps (inputs chained in registers) ----
    #pragma unroll 1
    for (int t = 0; t < PRED_LEN; t++) {
        lstm_step<true>(sm, wbase, gid, tig, px, py, pb0, pb1,
                        out + (size_t)t * BATCHN * 2, gbase);
    }
}

// ---------------------------------------------------------------------------
// Launch
// ---------------------------------------------------------------------------
extern "C" void kernel_launch(void* const* d_in, const int* in_sizes, int n_in,
                              void* d_out, int out_size)
{
    // metadata order: 0 obs_traj(unused), 1 obs_traj_rel,
    // 2..7 enc{emb_w,emb_b,w_ih,w_hh,b_ih,b_hh}, 8..13 dec{...}, 14 h2p_w, 15 h2p_b
    const float* obs_rel = (const float*)d_in[1];

    vlstm_prep<<<1, 256>>>(
        (const float*)d_in[2],  (const float*)d_in[3],
        (const float*)d_in[4],  (const float*)d_in[5],
        (const float*)d_in[6],  (const float*)d_in[7],
        (const float*)d_in[8],  (const float*)d_in[9],
        (const float*)d_in[10], (const float*)d_in[11],
        (const float*)d_in[12], (const float*)d_in[13]);

    const size_t smem = (size_t)SF_TOT * sizeof(float);   // ~208 KB
    cudaFuncSetAttribute(vlstm_main, cudaFuncAttributeMaxDynamicSharedMemorySize, (int)smem);
    vlstm_main<<<BATCHN / EPB, BLK, smem>>>(
        obs_rel, (const float*)d_in[14], (const float*)d_in[15], (float*)d_out);
}